// round 9
// baseline (speedup 1.0000x reference)
#include <cuda_runtime.h>
#include <math.h>
#include <stdint.h>

#define U_TOK 2048
#define D_MODEL 2048
#define NH 16
#define DH 128
#define DFF 8192
#define EPSF 1e-6f

// ---------------- scratch (static device globals; no allocations) ----------------
__device__ float g_h   [U_TOK * D_MODEL];
__device__ float g_q   [U_TOK * D_MODEL];
__device__ float g_k   [U_TOK * D_MODEL];
__device__ float g_v   [U_TOK * D_MODEL];      // stored TRANSPOSED: Vt[D][U]
__device__ float g_sc  [(size_t)NH * U_TOK * U_TOK];   // 256 MB attention scores
__device__ float g_rinv[NH * U_TOK];
__device__ float g_ao  [U_TOK * D_MODEL];
__device__ float g_x1  [U_TOK * D_MODEL];
__device__ float g_h2  [U_TOK * D_MODEL];
__device__ float g_ff  [U_TOK * DFF];
// tf32-rounded weight copies
__device__ float g_wqr [D_MODEL * D_MODEL];
__device__ float g_wkr [D_MODEL * D_MODEL];
__device__ float g_wvr [D_MODEL * D_MODEL];
__device__ float g_wor [D_MODEL * D_MODEL];
__device__ float g_wupr[DFF * D_MODEL];
__device__ float g_wdnr[D_MODEL * DFF];

// ---------------- helpers ----------------
__device__ __forceinline__ float warpSum(float v) {
    #pragma unroll
    for (int o = 16; o > 0; o >>= 1) v += __shfl_xor_sync(0xffffffffu, v, o);
    return v;
}
__device__ __forceinline__ float warpMax(float v) {
    #pragma unroll
    for (int o = 16; o > 0; o >>= 1) v = fmaxf(v, __shfl_xor_sync(0xffffffffu, v, o));
    return v;
}
__device__ __forceinline__ void cpasync16(void* s, const void* g) {
    uint32_t sa = (uint32_t)__cvta_generic_to_shared(s);
    asm volatile("cp.async.ca.shared.global [%0], [%1], 16;\n" :: "r"(sa), "l"(g));
}
__device__ __forceinline__ float round_tf32f(float f) {
    uint32_t r;
    asm volatile("cvt.rna.tf32.f32 %0, %1;" : "=r"(r) : "f"(f));
    return __uint_as_float(r);
}
__device__ __forceinline__ void mma_tf32(float* d, const uint32_t* a, const uint32_t* b) {
    asm volatile(
        "mma.sync.aligned.m16n8k8.row.col.f32.tf32.tf32.f32 "
        "{%0,%1,%2,%3}, {%4,%5,%6,%7}, {%8,%9}, {%0,%1,%2,%3};\n"
        : "+f"(d[0]), "+f"(d[1]), "+f"(d[2]), "+f"(d[3])
        : "r"(a[0]), "r"(a[1]), "r"(a[2]), "r"(a[3]), "r"(b[0]), "r"(b[1]));
}

// ---------------- weight tf32 pre-round (float4 grid-stride) ----------------
__global__ __launch_bounds__(256) void round_weights_kernel(
    const float* __restrict__ in, float* __restrict__ out, int n4)
{
    const int stride = gridDim.x * 256;
    for (int i = blockIdx.x * 256 + threadIdx.x; i < n4; i += stride) {
        float4 v = reinterpret_cast<const float4*>(in)[i];
        v.x = round_tf32f(v.x); v.y = round_tf32f(v.y);
        v.z = round_tf32f(v.z); v.w = round_tf32f(v.w);
        reinterpret_cast<float4*>(out)[i] = v;
    }
}

// ---------------- rmsnorm (tf32-rounded output: feeds GEMMs) ----------------
__global__ __launch_bounds__(256) void rmsnorm_kernel(
    const float* __restrict__ x, const float* __restrict__ w, float* __restrict__ out)
{
    const int row = blockIdx.x;
    const float* xr = x + (size_t)row * D_MODEL;
    float* orow = out + (size_t)row * D_MODEL;
    const int tid = threadIdx.x;

    float ss = 0.f;
    #pragma unroll
    for (int i = tid; i < D_MODEL; i += 256) { float v = xr[i]; ss = fmaf(v, v, ss); }

    __shared__ float red[8];
    float s = warpSum(ss);
    if ((tid & 31) == 0) red[tid >> 5] = s;
    __syncthreads();
    if (tid < 32) {
        float t = (tid < 8) ? red[tid] : 0.f;
        t = warpSum(t);
        if (tid == 0) red[0] = rsqrtf(t * (1.f / D_MODEL) + EPSF);
    }
    __syncthreads();
    const float inv = red[0];
    #pragma unroll
    for (int i = tid; i < D_MODEL; i += 256) orow[i] = round_tf32f(xr[i] * inv * w[i]);
}

// ---------------- softmax (exp only, tf32-rounded; stores 1/rowsum) ----------------
__global__ __launch_bounds__(256) void softmax_kernel(float* __restrict__ S, float* __restrict__ rinv)
{
    float* p = S + (size_t)blockIdx.x * U_TOK;
    const int tid = threadIdx.x;
    __shared__ float red[8];

    float m = -3.4e38f;
    #pragma unroll
    for (int i = tid; i < U_TOK; i += 256) m = fmaxf(m, p[i]);
    m = warpMax(m);
    if ((tid & 31) == 0) red[tid >> 5] = m;
    __syncthreads();
    if (tid < 32) {
        float t = (tid < 8) ? red[tid] : -3.4e38f;
        t = warpMax(t);
        if (tid == 0) red[0] = t;
    }
    __syncthreads();
    const float rowmax = red[0];
    __syncthreads();

    float s = 0.f;
    #pragma unroll
    for (int i = tid; i < U_TOK; i += 256) {
        float e = round_tf32f(__expf(p[i] - rowmax));
        p[i] = e;
        s += e;
    }
    s = warpSum(s);
    if ((tid & 31) == 0) red[tid >> 5] = s;
    __syncthreads();
    if (tid < 32) {
        float t = (tid < 8) ? red[tid] : 0.f;
        t = warpSum(t);
        if (tid == 0) rinv[blockIdx.x] = 1.f / t;
    }
}

// ---------------- TF32 tensor-core GEMM: C[M,N] = A[M,K] * B[N,K]^T ----------------
// Block 128x128, k-tile 16, 4 warps @ 64x64, 3-stage cp.async pipeline, 1 sync/iter.
// All A/B inputs MUST already be tf32-rounded (raw bits fed to mma).
// Epilogues: 0 none; 1 v*scale+aux1[r,c]; 2 v+aux1[r,c]; 3 gelu(v+aux2[c]);
//            4 aux1[r,c]+v+aux2[c]; 5 v*aux1[z*U+r]
// RS=1: tf32-round stored values (output feeds another GEMM). TRANS=1: C[c*ldc+r].
#define LDP 20
#define STG_F (128 * LDP)       // floats per stage per matrix
#define SMEM_BYTES (6 * STG_F * 4)

template<int EPI, int TRANS, int RS>
__global__ __launch_bounds__(128, 2) void mma_gemm(
    const float* __restrict__ A, const float* __restrict__ B, float* __restrict__ C,
    int K, int lda, int ldb, int ldc,
    size_t sA, size_t sB, size_t sC,
    const float* __restrict__ aux1, int ldaux,
    const float* __restrict__ aux2, float scale)
{
    A += (size_t)blockIdx.z * sA;
    B += (size_t)blockIdx.z * sB;
    C += (size_t)blockIdx.z * sC;

    extern __shared__ float sm[];
    float* As = sm;                 // [3][STG_F]
    float* Bs = sm + 3 * STG_F;     // [3][STG_F]

    const int tid  = threadIdx.x;
    const int lane = tid & 31;
    const int warp = tid >> 5;
    const int wm = (warp & 1) * 64;
    const int wn = (warp >> 1) * 64;
    const int bm = blockIdx.y * 128;
    const int bn = blockIdx.x * 128;
    const int tr = lane >> 2;
    const int tc = lane & 3;

    const int lr = tid >> 2;            // 0..31
    const int lc = (tid & 3) * 4;       // 0,4,8,12

    float acc[4][8][4] = {};

    const float* Ag = A + (size_t)(bm + lr) * lda + lc;
    const float* Bg = B + (size_t)(bn + lr) * ldb + lc;

    const int niter = K / 16;

    auto prefetch = [&](int stage, int k0) {
        float* a0 = &As[stage * STG_F + lr * LDP + lc];
        float* b0 = &Bs[stage * STG_F + lr * LDP + lc];
        #pragma unroll
        for (int j = 0; j < 4; ++j) {
            cpasync16(a0 + j * 32 * LDP, Ag + (size_t)(j * 32) * lda + k0);
            cpasync16(b0 + j * 32 * LDP, Bg + (size_t)(j * 32) * ldb + k0);
        }
        asm volatile("cp.async.commit_group;\n");
    };

    prefetch(0, 0);
    if (niter > 1) prefetch(1, 16);

    for (int it = 0; it < niter; ++it) {
        if (it + 1 < niter) { asm volatile("cp.async.wait_group 1;\n"); }
        else               { asm volatile("cp.async.wait_group 0;\n"); }
        __syncthreads();

        if (it + 2 < niter) prefetch((it + 2) % 3, (it + 2) * 16);

        const int si = it % 3;
        const uint32_t* Asb = reinterpret_cast<const uint32_t*>(As + si * STG_F);
        const uint32_t* Bsb = reinterpret_cast<const uint32_t*>(Bs + si * STG_F);

        #pragma unroll
        for (int ks = 0; ks < 2; ++ks) {
            const int k8 = ks * 8;
            uint32_t afr[4][4];
            #pragma unroll
            for (int mi = 0; mi < 4; ++mi) {
                const int base = (wm + mi * 16 + tr) * LDP + k8 + tc;
                afr[mi][0] = Asb[base];
                afr[mi][1] = Asb[base + 8 * LDP];
                afr[mi][2] = Asb[base + 4];
                afr[mi][3] = Asb[base + 8 * LDP + 4];
            }
            uint32_t bfr[8][2];
            #pragma unroll
            for (int ni = 0; ni < 8; ++ni) {
                const int base = (wn + ni * 8 + tr) * LDP + k8 + tc;
                bfr[ni][0] = Bsb[base];
                bfr[ni][1] = Bsb[base + 4];
            }
            #pragma unroll
            for (int mi = 0; mi < 4; ++mi)
                #pragma unroll
                for (int ni = 0; ni < 8; ++ni)
                    mma_tf32(acc[mi][ni], afr[mi], bfr[ni]);
        }
    }
    // NOTE: no trailing syncthreads needed; each thread's accumulators are private.

    // ---------------- epilogue ----------------
    #pragma unroll
    for (int mi = 0; mi < 4; ++mi) {
        #pragma unroll
        for (int ni = 0; ni < 8; ++ni) {
            const int row0 = bm + wm + mi * 16 + tr;
            const int col0 = bn + wn + ni * 8 + tc * 2;
            #pragma unroll
            for (int half = 0; half < 2; ++half) {
                const int row = row0 + half * 8;
                float e0 = acc[mi][ni][half * 2 + 0];
                float e1 = acc[mi][ni][half * 2 + 1];
                if (EPI == 1) {
                    e0 = fmaf(e0, scale, aux1[(size_t)row * ldaux + col0]);
                    e1 = fmaf(e1, scale, aux1[(size_t)row * ldaux + col0 + 1]);
                } else if (EPI == 2) {
                    e0 += aux1[(size_t)row * ldaux + col0];
                    e1 += aux1[(size_t)row * ldaux + col0 + 1];
                } else if (EPI == 3) {
                    e0 += aux2[col0];     e1 += aux2[col0 + 1];
                    e0 = 0.5f * e0 * (1.f + erff(e0 * 0.70710678118654752f));
                    e1 = 0.5f * e1 * (1.f + erff(e1 * 0.70710678118654752f));
                } else if (EPI == 4) {
                    e0 = aux1[(size_t)row * ldaux + col0]     + e0 + aux2[col0];
                    e1 = aux1[(size_t)row * ldaux + col0 + 1] + e1 + aux2[col0 + 1];
                } else if (EPI == 5) {
                    const float rs = aux1[(size_t)blockIdx.z * U_TOK + row];
                    e0 *= rs; e1 *= rs;
                }
                if (RS) { e0 = round_tf32f(e0); e1 = round_tf32f(e1); }
                if (TRANS) {
                    C[(size_t)col0 * ldc + row]       = e0;
                    C[(size_t)(col0 + 1) * ldc + row] = e1;
                } else {
                    *reinterpret_cast<float2*>(&C[(size_t)row * ldc + col0]) = make_float2(e0, e1);
                }
            }
        }
    }
}

// ---------------- launch ----------------
extern "C" void kernel_launch(void* const* d_in, const int* in_sizes, int n_in,
                              void* d_out, int out_size)
{
    const float* x    = (const float*)d_in[0];
    const float* adj  = (const float*)d_in[1];
    const float* n1w  = (const float*)d_in[2];
    const float* n2w  = (const float*)d_in[3];
    const float* wq   = (const float*)d_in[4];
    const float* wk   = (const float*)d_in[5];
    const float* wv   = (const float*)d_in[6];
    const float* wo   = (const float*)d_in[7];
    const float* wup  = (const float*)d_in[8];
    const float* bup  = (const float*)d_in[9];
    const float* wdn  = (const float*)d_in[10];
    const float* bdn  = (const float*)d_in[11];
    float* out = (float*)d_out;

    float *h, *q, *k, *v, *sc, *rinv, *ao, *x1, *h2, *ff;
    float *wqr, *wkr, *wvr, *wor, *wupr, *wdnr;
    cudaGetSymbolAddress((void**)&h,    g_h);
    cudaGetSymbolAddress((void**)&q,    g_q);
    cudaGetSymbolAddress((void**)&k,    g_k);
    cudaGetSymbolAddress((void**)&v,    g_v);
    cudaGetSymbolAddress((void**)&sc,   g_sc);
    cudaGetSymbolAddress((void**)&rinv, g_rinv);
    cudaGetSymbolAddress((void**)&ao,   g_ao);
    cudaGetSymbolAddress((void**)&x1,   g_x1);
    cudaGetSymbolAddress((void**)&h2,   g_h2);
    cudaGetSymbolAddress((void**)&ff,   g_ff);
    cudaGetSymbolAddress((void**)&wqr,  g_wqr);
    cudaGetSymbolAddress((void**)&wkr,  g_wkr);
    cudaGetSymbolAddress((void**)&wvr,  g_wvr);
    cudaGetSymbolAddress((void**)&wor,  g_wor);
    cudaGetSymbolAddress((void**)&wupr, g_wupr);
    cudaGetSymbolAddress((void**)&wdnr, g_wdnr);

    // raise dynamic smem limit for all GEMM instantiations (idempotent)
    cudaFuncSetAttribute(mma_gemm<0,0,1>, cudaFuncAttributeMaxDynamicSharedMemorySize, SMEM_BYTES);
    cudaFuncSetAttribute(mma_gemm<0,1,1>, cudaFuncAttributeMaxDynamicSharedMemorySize, SMEM_BYTES);
    cudaFuncSetAttribute(mma_gemm<1,0,0>, cudaFuncAttributeMaxDynamicSharedMemorySize, SMEM_BYTES);
    cudaFuncSetAttribute(mma_gemm<5,0,1>, cudaFuncAttributeMaxDynamicSharedMemorySize, SMEM_BYTES);
    cudaFuncSetAttribute(mma_gemm<2,0,0>, cudaFuncAttributeMaxDynamicSharedMemorySize, SMEM_BYTES);
    cudaFuncSetAttribute(mma_gemm<3,0,1>, cudaFuncAttributeMaxDynamicSharedMemorySize, SMEM_BYTES);
    cudaFuncSetAttribute(mma_gemm<4,0,0>, cudaFuncAttributeMaxDynamicSharedMemorySize, SMEM_BYTES);

    const float scale = 1.f / sqrtf((float)DH);

    // 0. pre-round weights to tf32
    round_weights_kernel<<<2048, 256>>>(wq,  wqr,  D_MODEL * D_MODEL / 4);
    round_weights_kernel<<<2048, 256>>>(wk,  wkr,  D_MODEL * D_MODEL / 4);
    round_weights_kernel<<<2048, 256>>>(wv,  wvr,  D_MODEL * D_MODEL / 4);
    round_weights_kernel<<<2048, 256>>>(wo,  wor,  D_MODEL * D_MODEL / 4);
    round_weights_kernel<<<4096, 256>>>(wup, wupr, DFF * D_MODEL / 4);
    round_weights_kernel<<<4096, 256>>>(wdn, wdnr, D_MODEL * DFF / 4);

    // 1. h = rmsnorm(x) (tf32-rounded)
    rmsnorm_kernel<<<U_TOK, 256>>>(x, n1w, h);

    // 2. Q/K/V projections (V stored transposed)
    dim3 gDD(D_MODEL / 128, U_TOK / 128, 1);
    mma_gemm<0,0,1><<<gDD, 128, SMEM_BYTES>>>(h, wqr, q, D_MODEL, D_MODEL, D_MODEL, D_MODEL,
                                              0, 0, 0, nullptr, 0, nullptr, 0.f);
    mma_gemm<0,0,1><<<gDD, 128, SMEM_BYTES>>>(h, wkr, k, D_MODEL, D_MODEL, D_MODEL, D_MODEL,
                                              0, 0, 0, nullptr, 0, nullptr, 0.f);
    mma_gemm<0,1,1><<<gDD, 128, SMEM_BYTES>>>(h, wvr, v, D_MODEL, D_MODEL, D_MODEL, U_TOK,
                                              0, 0, 0, nullptr, 0, nullptr, 0.f);

    // 3. scores = Q K^T * scale + adj
    dim3 gS(U_TOK / 128, U_TOK / 128, NH);
    mma_gemm<1,0,0><<<gS, 128, SMEM_BYTES>>>(q, k, sc, DH, D_MODEL, D_MODEL, U_TOK,
                                             (size_t)DH, (size_t)DH, (size_t)U_TOK * U_TOK,
                                             adj, U_TOK, nullptr, scale);

    // 4. softmax (exp + 1/rowsum)
    softmax_kernel<<<NH * U_TOK, 256>>>(sc, rinv);

    // 5. ao = P V (normalized in epilogue, tf32-rounded store)
    dim3 gP(DH / 128, U_TOK / 128, NH);
    mma_gemm<5,0,1><<<gP, 128, SMEM_BYTES>>>(sc, v, ao, U_TOK, U_TOK, U_TOK, D_MODEL,
                                             (size_t)U_TOK * U_TOK, (size_t)DH * U_TOK, (size_t)DH,
                                             rinv, 0, nullptr, 0.f);

    // 6. x1 = x + ao @ wo^T   (fp32 store: feeds rmsnorm + residual)
    mma_gemm<2,0,0><<<gDD, 128, SMEM_BYTES>>>(ao, wor, x1, D_MODEL, D_MODEL, D_MODEL, D_MODEL,
                                              0, 0, 0, x, D_MODEL, nullptr, 0.f);

    // 7. h2 = rmsnorm(x1) (tf32-rounded)
    rmsnorm_kernel<<<U_TOK, 256>>>(x1, n2w, h2);

    // 8. ff = gelu(h2 @ wup^T + bup) (tf32-rounded)
    dim3 gU(DFF / 128, U_TOK / 128, 1);
    mma_gemm<3,0,1><<<gU, 128, SMEM_BYTES>>>(h2, wupr, ff, D_MODEL, D_MODEL, D_MODEL, DFF,
                                             0, 0, 0, nullptr, 0, bup, 0.f);

    // 9. out = x1 + ff @ wdn^T + bdn  (fp32)
    mma_gemm<4,0,0><<<gDD, 128, SMEM_BYTES>>>(ff, wdnr, out, DFF, DFF, DFF, D_MODEL,
                                              0, 0, 0, x1, D_MODEL, bdn, 0.f);
}

// round 11
// speedup vs baseline: 1.3534x; 1.3534x over previous
#include <cuda_runtime.h>
#include <math.h>
#include <stdint.h>

#define U_TOK 2048
#define D_MODEL 2048
#define NH 16
#define DH 128
#define DFF 8192
#define EPSF 1e-6f

// ---------------- scratch (static device globals; no allocations) ----------------
__device__ float g_h   [U_TOK * D_MODEL];
__device__ float g_q   [U_TOK * D_MODEL];
__device__ float g_k   [U_TOK * D_MODEL];
__device__ float g_v   [U_TOK * D_MODEL];      // stored TRANSPOSED: Vt[D][U]
__device__ float g_sc  [(size_t)NH * U_TOK * U_TOK];
__device__ float g_rinv[NH * U_TOK];
__device__ float g_ao  [U_TOK * D_MODEL];
__device__ float g_x1  [U_TOK * D_MODEL];
__device__ float g_h2  [U_TOK * D_MODEL];
__device__ float g_ff  [U_TOK * DFF];
// tf32-rounded weight copies
__device__ float g_wqr [D_MODEL * D_MODEL];
__device__ float g_wkr [D_MODEL * D_MODEL];
__device__ float g_wvr [D_MODEL * D_MODEL];
__device__ float g_wor [D_MODEL * D_MODEL];
__device__ float g_wupr[DFF * D_MODEL];
__device__ float g_wdnr[D_MODEL * DFF];

// ---------------- helpers ----------------
__device__ __forceinline__ float warpSum(float v) {
    #pragma unroll
    for (int o = 16; o > 0; o >>= 1) v += __shfl_xor_sync(0xffffffffu, v, o);
    return v;
}
__device__ __forceinline__ float warpMax(float v) {
    #pragma unroll
    for (int o = 16; o > 0; o >>= 1) v = fmaxf(v, __shfl_xor_sync(0xffffffffu, v, o));
    return v;
}
__device__ __forceinline__ void cpasync16(void* s, const void* g) {
    uint32_t sa = (uint32_t)__cvta_generic_to_shared(s);
    asm volatile("cp.async.ca.shared.global [%0], [%1], 16;\n" :: "r"(sa), "l"(g));
}
__device__ __forceinline__ float round_tf32f(float f) {
    uint32_t r;
    asm volatile("cvt.rna.tf32.f32 %0, %1;" : "=r"(r) : "f"(f));
    return __uint_as_float(r);
}
__device__ __forceinline__ void mma_tf32(float* d, const uint32_t* a, const uint32_t* b) {
    asm volatile(
        "mma.sync.aligned.m16n8k8.row.col.f32.tf32.tf32.f32 "
        "{%0,%1,%2,%3}, {%4,%5,%6,%7}, {%8,%9}, {%0,%1,%2,%3};\n"
        : "+f"(d[0]), "+f"(d[1]), "+f"(d[2]), "+f"(d[3])
        : "r"(a[0]), "r"(a[1]), "r"(a[2]), "r"(a[3]), "r"(b[0]), "r"(b[1]));
}

// ---------------- weight tf32 pre-round ----------------
__global__ __launch_bounds__(256) void round_weights_kernel(
    const float* __restrict__ in, float* __restrict__ out, int n4)
{
    const int stride = gridDim.x * 256;
    for (int i = blockIdx.x * 256 + threadIdx.x; i < n4; i += stride) {
        float4 v = reinterpret_cast<const float4*>(in)[i];
        v.x = round_tf32f(v.x); v.y = round_tf32f(v.y);
        v.z = round_tf32f(v.z); v.w = round_tf32f(v.w);
        reinterpret_cast<float4*>(out)[i] = v;
    }
}

// ---------------- rmsnorm (tf32-rounded output) ----------------
__global__ __launch_bounds__(256) void rmsnorm_kernel(
    const float* __restrict__ x, const float* __restrict__ w, float* __restrict__ out)
{
    const int row = blockIdx.x;
    const float* xr = x + (size_t)row * D_MODEL;
    float* orow = out + (size_t)row * D_MODEL;
    const int tid = threadIdx.x;

    float ss = 0.f;
    #pragma unroll
    for (int i = tid; i < D_MODEL; i += 256) { float v = xr[i]; ss = fmaf(v, v, ss); }

    __shared__ float red[8];
    float s = warpSum(ss);
    if ((tid & 31) == 0) red[tid >> 5] = s;
    __syncthreads();
    if (tid < 32) {
        float t = (tid < 8) ? red[tid] : 0.f;
        t = warpSum(t);
        if (tid == 0) red[0] = rsqrtf(t * (1.f / D_MODEL) + EPSF);
    }
    __syncthreads();
    const float inv = red[0];
    #pragma unroll
    for (int i = tid; i < D_MODEL; i += 256) orow[i] = round_tf32f(xr[i] * inv * w[i]);
}

// ---------------- softmax (exp only, tf32-rounded; stores 1/rowsum) ----------------
__global__ __launch_bounds__(256) void softmax_kernel(float* __restrict__ S, float* __restrict__ rinv)
{
    float* p = S + (size_t)blockIdx.x * U_TOK;
    const int tid = threadIdx.x;
    __shared__ float red[8];

    float m = -3.4e38f;
    #pragma unroll
    for (int i = tid; i < U_TOK; i += 256) m = fmaxf(m, p[i]);
    m = warpMax(m);
    if ((tid & 31) == 0) red[tid >> 5] = m;
    __syncthreads();
    if (tid < 32) {
        float t = (tid < 8) ? red[tid] : -3.4e38f;
        t = warpMax(t);
        if (tid == 0) red[0] = t;
    }
    __syncthreads();
    const float rowmax = red[0];
    __syncthreads();

    float s = 0.f;
    #pragma unroll
    for (int i = tid; i < U_TOK; i += 256) {
        float e = round_tf32f(__expf(p[i] - rowmax));
        p[i] = e;
        s += e;
    }
    s = warpSum(s);
    if ((tid & 31) == 0) red[tid >> 5] = s;
    __syncthreads();
    if (tid < 32) {
        float t = (tid < 8) ? red[tid] : 0.f;
        t = warpSum(t);
        if (tid == 0) rinv[blockIdx.x] = 1.f / t;
    }
}

// ---------------- TF32 tensor-core GEMM: C[M,N] = A[M,K] * B[N,K]^T ----------------
// Block 128x128, k-tile 16, 8 warps (4x2) @ 32x64, 3-stage cp.async ring, 1 sync/iter.
// All A/B inputs MUST be pre-rounded to tf32 (raw bits fed to mma; no in-loop cvt).
// Epilogues: 0 none; 1 v*scale+aux1[r,c]; 2 v+aux1[r,c]; 3 gelu(v+aux2[c]);
//            4 aux1[r,c]+v+aux2[c]; 5 v*aux1[z*U+r]
// RS=1: tf32-round stored values. TRANS=1: C[c*ldc+r].
#define LDP 20
#define STG_F (128 * LDP)
#define SMEM_BYTES (6 * STG_F * 4)

template<int EPI, int TRANS, int RS>
__global__ __launch_bounds__(256, 2) void mma_gemm(
    const float* __restrict__ A, const float* __restrict__ B, float* __restrict__ C,
    int K, int lda, int ldb, int ldc,
    size_t sA, size_t sB, size_t sC,
    const float* __restrict__ aux1, int ldaux,
    const float* __restrict__ aux2, float scale)
{
    A += (size_t)blockIdx.z * sA;
    B += (size_t)blockIdx.z * sB;
    C += (size_t)blockIdx.z * sC;

    extern __shared__ float sm[];
    float* As = sm;                 // [3][STG_F]
    float* Bs = sm + 3 * STG_F;

    const int tid  = threadIdx.x;
    const int lane = tid & 31;
    const int warp = tid >> 5;
    const int wm = (warp & 3) * 32;
    const int wn = (warp >> 2) * 64;
    const int bm = blockIdx.y * 128;
    const int bn = blockIdx.x * 128;
    const int tr = lane >> 2;
    const int tc = lane & 3;

    const int lr = tid >> 2;          // 0..63
    const int lc = (tid & 3) * 4;     // 0,4,8,12

    float acc[2][8][4] = {};

    const float* Ag = A + (size_t)(bm + lr) * lda + lc;
    const float* Bg = B + (size_t)(bn + lr) * ldb + lc;
    const size_t lda64 = (size_t)64 * lda;
    const size_t ldb64 = (size_t)64 * ldb;

    const int niter = K / 16;

    auto prefetch = [&](int stage, int k0) {
        float* a0 = &As[stage * STG_F + lr * LDP + lc];
        float* b0 = &Bs[stage * STG_F + lr * LDP + lc];
        cpasync16(a0,            Ag + k0);
        cpasync16(a0 + 64 * LDP, Ag + lda64 + k0);
        cpasync16(b0,            Bg + k0);
        cpasync16(b0 + 64 * LDP, Bg + ldb64 + k0);
        asm volatile("cp.async.commit_group;\n");
    };

    prefetch(0, 0);
    if (niter > 1) prefetch(1, 16);

    for (int it = 0; it < niter; ++it) {
        if (it + 1 < niter) { asm volatile("cp.async.wait_group 1;\n"); }
        else               { asm volatile("cp.async.wait_group 0;\n"); }
        __syncthreads();

        if (it + 2 < niter) prefetch((it + 2) % 3, (it + 2) * 16);

        const int si = it % 3;
        const uint32_t* Asb = reinterpret_cast<const uint32_t*>(As + si * STG_F);
        const uint32_t* Bsb = reinterpret_cast<const uint32_t*>(Bs + si * STG_F);

        #pragma unroll
        for (int ks = 0; ks < 2; ++ks) {
            const int k8 = ks * 8;
            uint32_t afr[2][4];
            #pragma unroll
            for (int mi = 0; mi < 2; ++mi) {
                const int base = (wm + mi * 16 + tr) * LDP + k8 + tc;
                afr[mi][0] = Asb[base];
                afr[mi][1] = Asb[base + 8 * LDP];
                afr[mi][2] = Asb[base + 4];
                afr[mi][3] = Asb[base + 8 * LDP + 4];
            }
            uint32_t bfr[8][2];
            #pragma unroll
            for (int ni = 0; ni < 8; ++ni) {
                const int base = (wn + ni * 8 + tr) * LDP + k8 + tc;
                bfr[ni][0] = Bsb[base];
                bfr[ni][1] = Bsb[base + 4];
            }
            #pragma unroll
            for (int mi = 0; mi < 2; ++mi)
                #pragma unroll
                for (int ni = 0; ni < 8; ++ni)
                    mma_tf32(acc[mi][ni], afr[mi], bfr[ni]);
        }
    }

    // ---------------- epilogue ----------------
    #pragma unroll
    for (int mi = 0; mi < 2; ++mi) {
        #pragma unroll
        for (int ni = 0; ni < 8; ++ni) {
            const int row0 = bm + wm + mi * 16 + tr;
            const int col0 = bn + wn + ni * 8 + tc * 2;
            #pragma unroll
            for (int half = 0; half < 2; ++half) {
                const int row = row0 + half * 8;
                float e0 = acc[mi][ni][half * 2 + 0];
                float e1 = acc[mi][ni][half * 2 + 1];
                if (EPI == 1) {
                    e0 = fmaf(e0, scale, aux1[(size_t)row * ldaux + col0]);
                    e1 = fmaf(e1, scale, aux1[(size_t)row * ldaux + col0 + 1]);
                } else if (EPI == 2) {
                    e0 += aux1[(size_t)row * ldaux + col0];
                    e1 += aux1[(size_t)row * ldaux + col0 + 1];
                } else if (EPI == 3) {
                    e0 += aux2[col0];     e1 += aux2[col0 + 1];
                    e0 = 0.5f * e0 * (1.f + erff(e0 * 0.70710678118654752f));
                    e1 = 0.5f * e1 * (1.f + erff(e1 * 0.70710678118654752f));
                } else if (EPI == 4) {
                    e0 = aux1[(size_t)row * ldaux + col0]     + e0 + aux2[col0];
                    e1 = aux1[(size_t)row * ldaux + col0 + 1] + e1 + aux2[col0 + 1];
                } else if (EPI == 5) {
                    const float rs = aux1[(size_t)blockIdx.z * U_TOK + row];
                    e0 *= rs; e1 *= rs;
                }
                if (RS) { e0 = round_tf32f(e0); e1 = round_tf32f(e1); }
                if (TRANS) {
                    C[(size_t)col0 * ldc + row]       = e0;
                    C[(size_t)(col0 + 1) * ldc + row] = e1;
                } else {
                    *reinterpret_cast<float2*>(&C[(size_t)row * ldc + col0]) = make_float2(e0, e1);
                }
            }
        }
    }
}

// ---------------- launch ----------------
extern "C" void kernel_launch(void* const* d_in, const int* in_sizes, int n_in,
                              void* d_out, int out_size)
{
    const float* x    = (const float*)d_in[0];
    const float* adj  = (const float*)d_in[1];
    const float* n1w  = (const float*)d_in[2];
    const float* n2w  = (const float*)d_in[3];
    const float* wq   = (const float*)d_in[4];
    const float* wk   = (const float*)d_in[5];
    const float* wv   = (const float*)d_in[6];
    const float* wo   = (const float*)d_in[7];
    const float* wup  = (const float*)d_in[8];
    const float* bup  = (const float*)d_in[9];
    const float* wdn  = (const float*)d_in[10];
    const float* bdn  = (const float*)d_in[11];
    float* out = (float*)d_out;

    float *h, *q, *k, *v, *sc, *rinv, *ao, *x1, *h2, *ff;
    float *wqr, *wkr, *wvr, *wor, *wupr, *wdnr;
    cudaGetSymbolAddress((void**)&h,    g_h);
    cudaGetSymbolAddress((void**)&q,    g_q);
    cudaGetSymbolAddress((void**)&k,    g_k);
    cudaGetSymbolAddress((void**)&v,    g_v);
    cudaGetSymbolAddress((void**)&sc,   g_sc);
    cudaGetSymbolAddress((void**)&rinv, g_rinv);
    cudaGetSymbolAddress((void**)&ao,   g_ao);
    cudaGetSymbolAddress((void**)&x1,   g_x1);
    cudaGetSymbolAddress((void**)&h2,   g_h2);
    cudaGetSymbolAddress((void**)&ff,   g_ff);
    cudaGetSymbolAddress((void**)&wqr,  g_wqr);
    cudaGetSymbolAddress((void**)&wkr,  g_wkr);
    cudaGetSymbolAddress((void**)&wvr,  g_wvr);
    cudaGetSymbolAddress((void**)&wor,  g_wor);
    cudaGetSymbolAddress((void**)&wupr, g_wupr);
    cudaGetSymbolAddress((void**)&wdnr, g_wdnr);

    cudaFuncSetAttribute(mma_gemm<0,0,1>, cudaFuncAttributeMaxDynamicSharedMemorySize, SMEM_BYTES);
    cudaFuncSetAttribute(mma_gemm<0,1,1>, cudaFuncAttributeMaxDynamicSharedMemorySize, SMEM_BYTES);
    cudaFuncSetAttribute(mma_gemm<1,0,0>, cudaFuncAttributeMaxDynamicSharedMemorySize, SMEM_BYTES);
    cudaFuncSetAttribute(mma_gemm<5,0,1>, cudaFuncAttributeMaxDynamicSharedMemorySize, SMEM_BYTES);
    cudaFuncSetAttribute(mma_gemm<2,0,0>, cudaFuncAttributeMaxDynamicSharedMemorySize, SMEM_BYTES);
    cudaFuncSetAttribute(mma_gemm<3,0,1>, cudaFuncAttributeMaxDynamicSharedMemorySize, SMEM_BYTES);
    cudaFuncSetAttribute(mma_gemm<4,0,0>, cudaFuncAttributeMaxDynamicSharedMemorySize, SMEM_BYTES);

    const float scale = 1.f / sqrtf((float)DH);

    // 0. pre-round weights to tf32
    round_weights_kernel<<<2048, 256>>>(wq,  wqr,  D_MODEL * D_MODEL / 4);
    round_weights_kernel<<<2048, 256>>>(wk,  wkr,  D_MODEL * D_MODEL / 4);
    round_weights_kernel<<<2048, 256>>>(wv,  wvr,  D_MODEL * D_MODEL / 4);
    round_weights_kernel<<<2048, 256>>>(wo,  wor,  D_MODEL * D_MODEL / 4);
    round_weights_kernel<<<4096, 256>>>(wup, wupr, DFF * D_MODEL / 4);
    round_weights_kernel<<<4096, 256>>>(wdn, wdnr, D_MODEL * DFF / 4);

    // 1. h = rmsnorm(x) (tf32-rounded)
    rmsnorm_kernel<<<U_TOK, 256>>>(x, n1w, h);

    // 2. Q/K/V projections (V stored transposed)
    dim3 gDD(D_MODEL / 128, U_TOK / 128, 1);
    mma_gemm<0,0,1><<<gDD, 256, SMEM_BYTES>>>(h, wqr, q, D_MODEL, D_MODEL, D_MODEL, D_MODEL,
                                              0, 0, 0, nullptr, 0, nullptr, 0.f);
    mma_gemm<0,0,1><<<gDD, 256, SMEM_BYTES>>>(h, wkr, k, D_MODEL, D_MODEL, D_MODEL, D_MODEL,
                                              0, 0, 0, nullptr, 0, nullptr, 0.f);
    mma_gemm<0,1,1><<<gDD, 256, SMEM_BYTES>>>(h, wvr, v, D_MODEL, D_MODEL, D_MODEL, U_TOK,
                                              0, 0, 0, nullptr, 0, nullptr, 0.f);

    // 3. scores = Q K^T * scale + adj
    dim3 gS(U_TOK / 128, U_TOK / 128, NH);
    mma_gemm<1,0,0><<<gS, 256, SMEM_BYTES>>>(q, k, sc, DH, D_MODEL, D_MODEL, U_TOK,
                                             (size_t)DH, (size_t)DH, (size_t)U_TOK * U_TOK,
                                             adj, U_TOK, nullptr, scale);

    // 4. softmax (exp + 1/rowsum)
    softmax_kernel<<<NH * U_TOK, 256>>>(sc, rinv);

    // 5. ao = P V (normalized in epilogue, tf32-rounded store)
    dim3 gP(DH / 128, U_TOK / 128, NH);
    mma_gemm<5,0,1><<<gP, 256, SMEM_BYTES>>>(sc, v, ao, U_TOK, U_TOK, U_TOK, D_MODEL,
                                             (size_t)U_TOK * U_TOK, (size_t)DH * U_TOK, (size_t)DH,
                                             rinv, 0, nullptr, 0.f);

    // 6. x1 = x + ao @ wo^T (fp32 store)
    mma_gemm<2,0,0><<<gDD, 256, SMEM_BYTES>>>(ao, wor, x1, D_MODEL, D_MODEL, D_MODEL, D_MODEL,
                                              0, 0, 0, x, D_MODEL, nullptr, 0.f);

    // 7. h2 = rmsnorm(x1) (tf32-rounded)
    rmsnorm_kernel<<<U_TOK, 256>>>(x1, n2w, h2);

    // 8. ff = gelu(h2 @ wup^T + bup) (tf32-rounded)
    dim3 gU(DFF / 128, U_TOK / 128, 1);
    mma_gemm<3,0,1><<<gU, 256, SMEM_BYTES>>>(h2, wupr, ff, D_MODEL, D_MODEL, D_MODEL, DFF,
                                             0, 0, 0, nullptr, 0, bup, 0.f);

    // 9. out = x1 + ff @ wdn^T + bdn (fp32)
    mma_gemm<4,0,0><<<gDD, 256, SMEM_BYTES>>>(ff, wdnr, out, DFF, DFF, DFF, D_MODEL,
                                              0, 0, 0, x1, D_MODEL, bdn, 0.f);
}

// round 12
// speedup vs baseline: 1.4335x; 1.0592x over previous
#include <cuda_runtime.h>
#include <math.h>
#include <stdint.h>

#define U_TOK 2048
#define D_MODEL 2048
#define NH 16
#define DH 128
#define DFF 8192
#define EPSF 1e-6f

// ---------------- scratch (static device globals; no allocations) ----------------
__device__ float g_h   [U_TOK * D_MODEL];
__device__ float g_q   [U_TOK * D_MODEL];
__device__ float g_k   [U_TOK * D_MODEL];      // k-proj output, PERMUTED cols (within-16)
__device__ float g_v   [U_TOK * D_MODEL];      // Vt[D][U], PERMUTED rows-within-16 (u dim)
__device__ float g_sc  [(size_t)NH * U_TOK * U_TOK];
__device__ float g_rinv[NH * U_TOK];
__device__ float g_ao  [U_TOK * D_MODEL];
__device__ float g_x1  [U_TOK * D_MODEL];
__device__ float g_h2  [U_TOK * D_MODEL];
__device__ float g_ff  [U_TOK * DFF];
// tf32-rounded + k-permuted weight copies
__device__ float g_wqr [D_MODEL * D_MODEL];
__device__ float g_wkr [D_MODEL * D_MODEL];
__device__ float g_wvr [D_MODEL * D_MODEL];
__device__ float g_wor [D_MODEL * D_MODEL];
__device__ float g_wupr[DFF * D_MODEL];
__device__ float g_wdnr[D_MODEL * DFF];

// ---------------- helpers ----------------
__device__ __forceinline__ float warpSum(float v) {
    #pragma unroll
    for (int o = 16; o > 0; o >>= 1) v += __shfl_xor_sync(0xffffffffu, v, o);
    return v;
}
__device__ __forceinline__ float warpMax(float v) {
    #pragma unroll
    for (int o = 16; o > 0; o >>= 1) v = fmaxf(v, __shfl_xor_sync(0xffffffffu, v, o));
    return v;
}
__device__ __forceinline__ void cpasync16(void* s, const void* g) {
    uint32_t sa = (uint32_t)__cvta_generic_to_shared(s);
    asm volatile("cp.async.ca.shared.global [%0], [%1], 16;\n" :: "r"(sa), "l"(g));
}
__device__ __forceinline__ float round_tf32f(float f) {
    uint32_t r;
    asm volatile("cvt.rna.tf32.f32 %0, %1;" : "=r"(r) : "f"(f));
    return __uint_as_float(r);
}
__device__ __forceinline__ int perm16(int j) {  // involution: 4a+b -> 4b+a
    return ((j & 3) << 2) | (j >> 2);
}
__device__ __forceinline__ void mma_tf32(float* d, const uint32_t* a, uint32_t b0, uint32_t b1) {
    asm volatile(
        "mma.sync.aligned.m16n8k8.row.col.f32.tf32.tf32.f32 "
        "{%0,%1,%2,%3}, {%4,%5,%6,%7}, {%8,%9}, {%0,%1,%2,%3};\n"
        : "+f"(d[0]), "+f"(d[1]), "+f"(d[2]), "+f"(d[3])
        : "r"(a[0]), "r"(a[1]), "r"(a[2]), "r"(a[3]), "r"(b0), "r"(b1));
}

// ---------------- weight prepass: tf32 round + within-16 k-permute (4x4 word transpose) ----------------
__global__ __launch_bounds__(256) void round_permute_weights_kernel(
    const float* __restrict__ in, float* __restrict__ out, int nblk16)
{
    const int stride = gridDim.x * 256;
    for (int i = blockIdx.x * 256 + threadIdx.x; i < nblk16; i += stride) {
        const float4* p = reinterpret_cast<const float4*>(in) + (size_t)i * 4;
        float4 c0 = p[0], c1 = p[1], c2 = p[2], c3 = p[3];
        float4 o0 = make_float4(round_tf32f(c0.x), round_tf32f(c1.x), round_tf32f(c2.x), round_tf32f(c3.x));
        float4 o1 = make_float4(round_tf32f(c0.y), round_tf32f(c1.y), round_tf32f(c2.y), round_tf32f(c3.y));
        float4 o2 = make_float4(round_tf32f(c0.z), round_tf32f(c1.z), round_tf32f(c2.z), round_tf32f(c3.z));
        float4 o3 = make_float4(round_tf32f(c0.w), round_tf32f(c1.w), round_tf32f(c2.w), round_tf32f(c3.w));
        float4* q = reinterpret_cast<float4*>(out) + (size_t)i * 4;
        q[0] = o0; q[1] = o1; q[2] = o2; q[3] = o3;
    }
}

// ---------------- rmsnorm (tf32-rounded output) ----------------
__global__ __launch_bounds__(256) void rmsnorm_kernel(
    const float* __restrict__ x, const float* __restrict__ w, float* __restrict__ out)
{
    const int row = blockIdx.x;
    const float* xr = x + (size_t)row * D_MODEL;
    float* orow = out + (size_t)row * D_MODEL;
    const int tid = threadIdx.x;

    float ss = 0.f;
    #pragma unroll
    for (int i = tid; i < D_MODEL; i += 256) { float v = xr[i]; ss = fmaf(v, v, ss); }

    __shared__ float red[8];
    float s = warpSum(ss);
    if ((tid & 31) == 0) red[tid >> 5] = s;
    __syncthreads();
    if (tid < 32) {
        float t = (tid < 8) ? red[tid] : 0.f;
        t = warpSum(t);
        if (tid == 0) red[0] = rsqrtf(t * (1.f / D_MODEL) + EPSF);
    }
    __syncthreads();
    const float inv = red[0];
    #pragma unroll
    for (int i = tid; i < D_MODEL; i += 256) orow[i] = round_tf32f(xr[i] * inv * w[i]);
}

// ---------------- softmax (exp only, tf32-rounded; stores 1/rowsum) ----------------
__global__ __launch_bounds__(256) void softmax_kernel(float* __restrict__ S, float* __restrict__ rinv)
{
    float* p = S + (size_t)blockIdx.x * U_TOK;
    const int tid = threadIdx.x;
    __shared__ float red[8];

    float m = -3.4e38f;
    #pragma unroll
    for (int i = tid; i < U_TOK; i += 256) m = fmaxf(m, p[i]);
    m = warpMax(m);
    if ((tid & 31) == 0) red[tid >> 5] = m;
    __syncthreads();
    if (tid < 32) {
        float t = (tid < 8) ? red[tid] : -3.4e38f;
        t = warpMax(t);
        if (tid == 0) red[0] = t;
    }
    __syncthreads();
    const float rowmax = red[0];
    __syncthreads();

    float s = 0.f;
    #pragma unroll
    for (int i = tid; i < U_TOK; i += 256) {
        float e = round_tf32f(__expf(p[i] - rowmax));
        p[i] = e;
        s += e;
    }
    s = warpSum(s);
    if ((tid & 31) == 0) red[tid >> 5] = s;
    __syncthreads();
    if (tid < 32) {
        float t = (tid < 8) ? red[tid] : 0.f;
        t = warpSum(t);
        if (tid == 0) rinv[blockIdx.x] = 1.f / t;
    }
}

// ---------------- TF32 tensor-core GEMM: C[M,N] = A[M,K] * B[N,K]^T ----------------
// B's k-dim must be PRE-PERMUTED within every 16-block by perm16 (weights prepass /
// producer epilogues do this). A is raw. B fragments load as single LDS.128.
// Block 128x128, k-tile 16, 8 warps (4x2) @ 32x64, 3-stage cp.async ring, 1 sync/iter.
// Epilogues: 0 none; 1 v*scale+aux1[r,c]; 2 v+aux1[r,c]; 3 gelu(v+aux2[c]);
//            4 aux1[r,c]+v+aux2[c]; 5 v*aux1[z*U+r]
// RS=1: tf32-round stores. TRANS=1: C[c*ldc+r]. PERM=1: permute contraction-producing
// dim of the OUTPUT within-16 (col if !TRANS, row if TRANS).
#define ALDP 20
#define ASTG_F (128 * ALDP)
#define BSTG_F (128 * 16)
#define SMEM_BYTES ((3 * ASTG_F + 3 * BSTG_F) * 4)

template<int EPI, int TRANS, int RS, int PERM>
__global__ __launch_bounds__(256, 2) void mma_gemm(
    const float* __restrict__ A, const float* __restrict__ B, float* __restrict__ C,
    int K, int lda, int ldb, int ldc,
    size_t sA, size_t sB, size_t sC,
    const float* __restrict__ aux1, int ldaux,
    const float* __restrict__ aux2, float scale)
{
    A += (size_t)blockIdx.z * sA;
    B += (size_t)blockIdx.z * sB;
    C += (size_t)blockIdx.z * sC;

    extern __shared__ float sm[];
    float* As = sm;                   // [3][ASTG_F], row stride 20
    float* Bs = sm + 3 * ASTG_F;      // [3][BSTG_F], row stride 16 (no pad)

    const int tid  = threadIdx.x;
    const int lane = tid & 31;
    const int warp = tid >> 5;
    const int wm = (warp & 3) * 32;
    const int wn = (warp >> 2) * 64;
    const int bm = blockIdx.y * 128;
    const int bn = blockIdx.x * 128;
    const int tr = lane >> 2;
    const int tc = lane & 3;

    const int lr = tid >> 2;          // 0..63
    const int lc = (tid & 3) * 4;     // 0,4,8,12

    float acc[2][8][4] = {};

    const float* Ag = A + (size_t)(bm + lr) * lda + lc;
    const float* Bg = B + (size_t)(bn + lr) * ldb + lc;
    const size_t lda64 = (size_t)64 * lda;
    const size_t ldb64 = (size_t)64 * ldb;

    const int niter = K / 16;

    auto prefetch = [&](int stage, int k0) {
        float* a0 = &As[stage * ASTG_F + lr * ALDP + lc];
        float* b0 = &Bs[stage * BSTG_F + lr * 16 + lc];
        cpasync16(a0,             Ag + k0);
        cpasync16(a0 + 64 * ALDP, Ag + lda64 + k0);
        cpasync16(b0,             Bg + k0);
        cpasync16(b0 + 64 * 16,   Bg + ldb64 + k0);
        asm volatile("cp.async.commit_group;\n");
    };

    prefetch(0, 0);
    if (niter > 1) prefetch(1, 16);

    for (int it = 0; it < niter; ++it) {
        if (it + 1 < niter) { asm volatile("cp.async.wait_group 1;\n"); }
        else               { asm volatile("cp.async.wait_group 0;\n"); }
        __syncthreads();

        if (it + 2 < niter) prefetch((it + 2) % 3, (it + 2) * 16);

        const int si = it % 3;
        const uint32_t* Asb = reinterpret_cast<const uint32_t*>(As + si * ASTG_F);
        const uint4*    Bsb = reinterpret_cast<const uint4*>(Bs + si * BSTG_F);

        // B fragments: one LDS.128 per ni covers BOTH k8 steps (permuted layout)
        uint4 bfr[8];
        #pragma unroll
        for (int ni = 0; ni < 8; ++ni)
            bfr[ni] = Bsb[(wn + ni * 8 + tr) * 4 + tc];

        #pragma unroll
        for (int ks = 0; ks < 2; ++ks) {
            const int k8 = ks * 8;
            uint32_t afr[2][4];
            #pragma unroll
            for (int mi = 0; mi < 2; ++mi) {
                const int base = (wm + mi * 16 + tr) * ALDP + k8 + tc;
                afr[mi][0] = Asb[base];
                afr[mi][1] = Asb[base + 8 * ALDP];
                afr[mi][2] = Asb[base + 4];
                afr[mi][3] = Asb[base + 8 * ALDP + 4];
            }
            #pragma unroll
            for (int mi = 0; mi < 2; ++mi)
                #pragma unroll
                for (int ni = 0; ni < 8; ++ni) {
                    if (ks == 0) mma_tf32(acc[mi][ni], afr[mi], bfr[ni].x, bfr[ni].y);
                    else         mma_tf32(acc[mi][ni], afr[mi], bfr[ni].z, bfr[ni].w);
                }
        }
    }

    // ---------------- epilogue ----------------
    #pragma unroll
    for (int mi = 0; mi < 2; ++mi) {
        #pragma unroll
        for (int ni = 0; ni < 8; ++ni) {
            const int row0 = bm + wm + mi * 16 + tr;
            const int col0 = bn + wn + ni * 8 + tc * 2;
            #pragma unroll
            for (int half = 0; half < 2; ++half) {
                const int row = row0 + half * 8;
                float e0 = acc[mi][ni][half * 2 + 0];
                float e1 = acc[mi][ni][half * 2 + 1];
                if (EPI == 1) {
                    e0 = fmaf(e0, scale, aux1[(size_t)row * ldaux + col0]);
                    e1 = fmaf(e1, scale, aux1[(size_t)row * ldaux + col0 + 1]);
                } else if (EPI == 2) {
                    e0 += aux1[(size_t)row * ldaux + col0];
                    e1 += aux1[(size_t)row * ldaux + col0 + 1];
                } else if (EPI == 3) {
                    e0 += aux2[col0];     e1 += aux2[col0 + 1];
                    e0 = 0.5f * e0 * (1.f + erff(e0 * 0.70710678118654752f));
                    e1 = 0.5f * e1 * (1.f + erff(e1 * 0.70710678118654752f));
                } else if (EPI == 4) {
                    e0 = aux1[(size_t)row * ldaux + col0]     + e0 + aux2[col0];
                    e1 = aux1[(size_t)row * ldaux + col0 + 1] + e1 + aux2[col0 + 1];
                } else if (EPI == 5) {
                    const float rs = aux1[(size_t)blockIdx.z * U_TOK + row];
                    e0 *= rs; e1 *= rs;
                }
                if (RS) { e0 = round_tf32f(e0); e1 = round_tf32f(e1); }
                if (TRANS) {
                    int r0 = row, r1 = row;  // row is the contraction dim of consumer
                    if (PERM) { r0 = (row & ~15) | perm16(row & 15); r1 = r0; }
                    C[(size_t)col0 * ldc + r0]       = e0;
                    C[(size_t)(col0 + 1) * ldc + r1] = e1;
                } else if (PERM) {
                    const int c0 = (col0 & ~15) | perm16(col0 & 15);
                    const int c1 = ((col0 + 1) & ~15) | perm16((col0 + 1) & 15);
                    C[(size_t)row * ldc + c0] = e0;
                    C[(size_t)row * ldc + c1] = e1;
                } else {
                    *reinterpret_cast<float2*>(&C[(size_t)row * ldc + col0]) = make_float2(e0, e1);
                }
            }
        }
    }
}

// ---------------- launch ----------------
extern "C" void kernel_launch(void* const* d_in, const int* in_sizes, int n_in,
                              void* d_out, int out_size)
{
    const float* x    = (const float*)d_in[0];
    const float* adj  = (const float*)d_in[1];
    const float* n1w  = (const float*)d_in[2];
    const float* n2w  = (const float*)d_in[3];
    const float* wq   = (const float*)d_in[4];
    const float* wk   = (const float*)d_in[5];
    const float* wv   = (const float*)d_in[6];
    const float* wo   = (const float*)d_in[7];
    const float* wup  = (const float*)d_in[8];
    const float* bup  = (const float*)d_in[9];
    const float* wdn  = (const float*)d_in[10];
    const float* bdn  = (const float*)d_in[11];
    float* out = (float*)d_out;

    float *h, *q, *k, *v, *sc, *rinv, *ao, *x1, *h2, *ff;
    float *wqr, *wkr, *wvr, *wor, *wupr, *wdnr;
    cudaGetSymbolAddress((void**)&h,    g_h);
    cudaGetSymbolAddress((void**)&q,    g_q);
    cudaGetSymbolAddress((void**)&k,    g_k);
    cudaGetSymbolAddress((void**)&v,    g_v);
    cudaGetSymbolAddress((void**)&sc,   g_sc);
    cudaGetSymbolAddress((void**)&rinv, g_rinv);
    cudaGetSymbolAddress((void**)&ao,   g_ao);
    cudaGetSymbolAddress((void**)&x1,   g_x1);
    cudaGetSymbolAddress((void**)&h2,   g_h2);
    cudaGetSymbolAddress((void**)&ff,   g_ff);
    cudaGetSymbolAddress((void**)&wqr,  g_wqr);
    cudaGetSymbolAddress((void**)&wkr,  g_wkr);
    cudaGetSymbolAddress((void**)&wvr,  g_wvr);
    cudaGetSymbolAddress((void**)&wor,  g_wor);
    cudaGetSymbolAddress((void**)&wupr, g_wupr);
    cudaGetSymbolAddress((void**)&wdnr, g_wdnr);

    cudaFuncSetAttribute(mma_gemm<0,0,1,0>, cudaFuncAttributeMaxDynamicSharedMemorySize, SMEM_BYTES);
    cudaFuncSetAttribute(mma_gemm<0,0,1,1>, cudaFuncAttributeMaxDynamicSharedMemorySize, SMEM_BYTES);
    cudaFuncSetAttribute(mma_gemm<0,1,1,1>, cudaFuncAttributeMaxDynamicSharedMemorySize, SMEM_BYTES);
    cudaFuncSetAttribute(mma_gemm<1,0,0,0>, cudaFuncAttributeMaxDynamicSharedMemorySize, SMEM_BYTES);
    cudaFuncSetAttribute(mma_gemm<5,0,1,0>, cudaFuncAttributeMaxDynamicSharedMemorySize, SMEM_BYTES);
    cudaFuncSetAttribute(mma_gemm<2,0,0,0>, cudaFuncAttributeMaxDynamicSharedMemorySize, SMEM_BYTES);
    cudaFuncSetAttribute(mma_gemm<3,0,1,0>, cudaFuncAttributeMaxDynamicSharedMemorySize, SMEM_BYTES);
    cudaFuncSetAttribute(mma_gemm<4,0,0,0>, cudaFuncAttributeMaxDynamicSharedMemorySize, SMEM_BYTES);

    const float scale = 1.f / sqrtf((float)DH);

    // 0. pre-round + k-permute weights (B operands of all GEMMs)
    round_permute_weights_kernel<<<2048, 256>>>(wq,  wqr,  D_MODEL * D_MODEL / 16);
    round_permute_weights_kernel<<<2048, 256>>>(wk,  wkr,  D_MODEL * D_MODEL / 16);
    round_permute_weights_kernel<<<2048, 256>>>(wv,  wvr,  D_MODEL * D_MODEL / 16);
    round_permute_weights_kernel<<<2048, 256>>>(wo,  wor,  D_MODEL * D_MODEL / 16);
    round_permute_weights_kernel<<<4096, 256>>>(wup, wupr, DFF * D_MODEL / 16);
    round_permute_weights_kernel<<<4096, 256>>>(wdn, wdnr, D_MODEL * DFF / 16);

    // 1. h = rmsnorm(x) (tf32-rounded, raw layout: A operand)
    rmsnorm_kernel<<<U_TOK, 256>>>(x, n1w, h);

    // 2. Q/K/V projections.
    //    Q: raw (A of scores). K: PERM cols (B of scores). V: TRANS + PERM rows (B of PV).
    dim3 gDD(D_MODEL / 128, U_TOK / 128, 1);
    mma_gemm<0,0,1,0><<<gDD, 256, SMEM_BYTES>>>(h, wqr, q, D_MODEL, D_MODEL, D_MODEL, D_MODEL,
                                                0, 0, 0, nullptr, 0, nullptr, 0.f);
    mma_gemm<0,0,1,1><<<gDD, 256, SMEM_BYTES>>>(h, wkr, k, D_MODEL, D_MODEL, D_MODEL, D_MODEL,
                                                0, 0, 0, nullptr, 0, nullptr, 0.f);
    mma_gemm<0,1,1,1><<<gDD, 256, SMEM_BYTES>>>(h, wvr, v, D_MODEL, D_MODEL, D_MODEL, U_TOK,
                                                0, 0, 0, nullptr, 0, nullptr, 0.f);

    // 3. scores = Q K^T * scale + adj   (B=g_k pre-permuted)
    dim3 gS(U_TOK / 128, U_TOK / 128, NH);
    mma_gemm<1,0,0,0><<<gS, 256, SMEM_BYTES>>>(q, k, sc, DH, D_MODEL, D_MODEL, U_TOK,
                                               (size_t)DH, (size_t)DH, (size_t)U_TOK * U_TOK,
                                               adj, U_TOK, nullptr, scale);

    // 4. softmax (exp + 1/rowsum)
    softmax_kernel<<<NH * U_TOK, 256>>>(sc, rinv);

    // 5. ao = P V (B=Vt pre-permuted over u), normalized + tf32-rounded
    dim3 gP(DH / 128, U_TOK / 128, NH);
    mma_gemm<5,0,1,0><<<gP, 256, SMEM_BYTES>>>(sc, v, ao, U_TOK, U_TOK, U_TOK, D_MODEL,
                                               (size_t)U_TOK * U_TOK, (size_t)DH * U_TOK, (size_t)DH,
                                               rinv, 0, nullptr, 0.f);

    // 6. x1 = x + ao @ wo^T (fp32 store)
    mma_gemm<2,0,0,0><<<gDD, 256, SMEM_BYTES>>>(ao, wor, x1, D_MODEL, D_MODEL, D_MODEL, D_MODEL,
                                                0, 0, 0, x, D_MODEL, nullptr, 0.f);

    // 7. h2 = rmsnorm(x1) (tf32-rounded)
    rmsnorm_kernel<<<U_TOK, 256>>>(x1, n2w, h2);

    // 8. ff = gelu(h2 @ wup^T + bup) (tf32-rounded)
    dim3 gU(DFF / 128, U_TOK / 128, 1);
    mma_gemm<3,0,1,0><<<gU, 256, SMEM_BYTES>>>(h2, wupr, ff, D_MODEL, D_MODEL, D_MODEL, DFF,
                                               0, 0, 0, nullptr, 0, bup, 0.f);

    // 9. out = x1 + ff @ wdn^T + bdn (fp32)
    mma_gemm<4,0,0,0><<<gDD, 256, SMEM_BYTES>>>(ff, wdnr, out, DFF, DFF, DFF, D_MODEL,
                                                0, 0, 0, x1, D_MODEL, bdn, 0.f);
}